// round 8
// baseline (speedup 1.0000x reference)
#include <cuda_runtime.h>
#include <cuda_bf16.h>

// PathSampling: smem-staged centrality prefix + PREDICATED (branch-free,
// non-generic) gather. 2 blocks/SM x 1024 thr = 64 warps/SM; each block
// stages TAB_N floats (112KB) of the table. Per kept position exactly one
// predicated load executes: LDS (id<TAB_N) or LDG.NC (id>=TAB_N). Masked
// positions (id==-1) execute neither. No BSSY, no generic LD.E.

#define TAB_N 28672  // floats staged per block (112 KB); 2 blocks/SM fit 224KB

__global__ __launch_bounds__(1024, 2) void path_sampling_kernel(
    const int*   __restrict__ paths,      // [n_node, 32, 8]
    const int*   __restrict__ edge_ids,   // [n_node, 32, 7]
    const int*   __restrict__ rand_lens,  // [n_node, 32]
    const float* __restrict__ centrality, // [n_graph]
    float*       __restrict__ out_paths,  // [n_node, 8, 8] float32
    float*       __restrict__ out_edges,  // [n_node, 8, 7] float32
    int n_node)
{
    extern __shared__ float tab[];

    // ---- stage table prefix into smem (coalesced float4) ----
    {
        const float4* src = reinterpret_cast<const float4*>(centrality);
        float4*       dst = reinterpret_cast<float4*>(tab);
        for (int i = threadIdx.x; i < TAB_N / 4; i += 1024)
            dst[i] = src[i];
    }
    __syncthreads();

    const unsigned tab_base = (unsigned)__cvta_generic_to_shared(tab);

    const int lane        = threadIdx.x & 31;
    const int warp_local  = threadIdx.x >> 5;
    const int total_warps = gridDim.x << 5;  // 32 warps per block

    for (int node = (blockIdx.x << 5) + warp_local;
         node < n_node; node += total_warps) {

        // ---- load this lane's path row (coalesced int4 x2) + length ----
        const int4* prow = reinterpret_cast<const int4*>(paths + (node * 32 + lane) * 8);
        int4 p0 = __ldg(prow + 0);
        int4 p1 = __ldg(prow + 1);
        const int len = __ldg(rand_lens + node * 32 + lane);

        int mp[8] = {p0.x, p0.y, p0.z, p0.w, p1.x, p1.y, p1.z, p1.w};

        // ---- mask first (-1), then predicated dual-path gather ----
        float score = 0.0f;
#pragma unroll
        for (int j = 0; j < 8; j++) {
            if (j > len) mp[j] = -1;
            int id = mp[j];
            unsigned saddr = tab_base + ((unsigned)id << 2);   // valid iff ps
            const float* gaddr = centrality + id;              // valid iff pg
            float v;
            asm volatile(
                "{\n\t"
                ".reg .pred ps, pg;\n\t"
                ".reg .f32 vs, vg;\n\t"
                "mov.f32 vs, 0f00000000;\n\t"
                "mov.f32 vg, 0f00000000;\n\t"
                "setp.lt.u32 ps, %1, %4;\n\t"     // 0 <= id < TAB_N (u32: -1 excluded)
                "setp.ge.s32 pg, %1, %4;\n\t"     // id >= TAB_N (s32: -1 excluded)
                "@ps ld.shared.f32 vs, [%2];\n\t"
                "@pg ld.global.nc.f32 vg, [%3];\n\t"
                "add.f32 %0, vs, vg;\n\t"
                "}"
                : "=f"(v)
                : "r"(id), "r"(saddr), "l"(gaddr), "n"(TAB_N));
            score += v;
        }

        // ---- stable rank: higher score first, tie -> lower lane ----
        int rank = 0;
#pragma unroll
        for (int j = 0; j < 32; j++) {
            float sj = __shfl_sync(0xffffffffu, score, j);
            rank += (sj > score) || (sj == score && j < lane);
        }

        // ---- slot -> source lane map (lane r holds src lane of rank r) ----
        int my_src = 0;
#pragma unroll
        for (int r = 0; r < 8; r++) {
            unsigned mr = __ballot_sync(0xffffffffu, rank == r);
            if (lane == r) my_src = __ffs(mr) - 1;
        }

        // ---- selected lanes write their path row (float32) ----
        if (rank < 8) {
            float4* op = reinterpret_cast<float4*>(out_paths + (node * 8 + rank) * 8);
            op[0] = make_float4((float)mp[0], (float)mp[1], (float)mp[2], (float)mp[3]);
            op[1] = make_float4((float)mp[4], (float)mp[5], (float)mp[6], (float)mp[7]);
        }

        // ---- warp-cooperative edge copy: 56 contiguous floats/node ----
        const int* ebase = edge_ids + node * (32 * 7);
        float*     obase = out_edges + node * 56;
#pragma unroll
        for (int pass = 0; pass < 2; pass++) {
            int e = lane + pass * 32;
            int s = e / 7;
            int j = e - s * 7;
            int src = __shfl_sync(0xffffffffu, my_src, s & 7);
            if (e < 56) {
                obase[e] = (float)__ldg(ebase + src * 7 + j);
            }
        }
    }
}

extern "C" void kernel_launch(void* const* d_in, const int* in_sizes, int n_in,
                              void* d_out, int out_size) {
    // Bind inputs by DESCENDING element count (all distinct, order-agnostic):
    //   paths 25.6M > edge_ids 22.4M > rand_lens 3.2M > centrality 100K;
    //   size-1 k_path scalar ignored (constant 8).
    int idx[8];
    int m = 0;
    for (int i = 0; i < n_in && m < 8; i++) {
        if (in_sizes[i] > 1) idx[m++] = i;
    }
    for (int a = 1; a < m; a++) {
        int v = idx[a];
        int b = a - 1;
        while (b >= 0 && in_sizes[idx[b]] < in_sizes[v]) { idx[b + 1] = idx[b]; b--; }
        idx[b + 1] = v;
    }

    const int*   paths      = (const int*)  d_in[idx[0]];
    const int*   edge_ids   = (const int*)  d_in[idx[1]];
    const int*   rand_lens  = (const int*)  d_in[idx[2]];
    const float* centrality = (const float*)d_in[idx[3]];

    const int n_node = in_sizes[idx[0]] / (32 * 8);

    float* out_paths = (float*)d_out;                       // [n_node, 8, 8]
    float* out_edges = out_paths + (long long)n_node * 64;  // [n_node, 8, 7]

    const int smem_bytes = TAB_N * (int)sizeof(float);      // 114,688 B

    static int configured = -1;
    if (configured < 0) {
        cudaFuncSetAttribute(path_sampling_kernel,
                             cudaFuncAttributeMaxDynamicSharedMemorySize,
                             smem_bytes);
        configured = 1;
    }

    int dev = 0, sm_count = 148;
    cudaGetDevice(&dev);
    cudaDeviceGetAttribute(&sm_count, cudaDevAttrMultiProcessorCount, dev);

    path_sampling_kernel<<<sm_count * 2, 1024, smem_bytes>>>(
        paths, edge_ids, rand_lens, centrality, out_paths, out_edges, n_node);
}

// round 9
// speedup vs baseline: 1.0989x; 1.0989x over previous
#include <cuda_runtime.h>
#include <cuda_bf16.h>

// PathSampling: smem-staged centrality prefix (224KB, 57% coverage), persistent
// 1 block/SM. Gather per kept position = LDS (clamped, always) + LDG (real tail
// element, or broadcast of centrality[0] for covered lanes) + SELP. All plain
// CUDA -> ptxas keeps MLP; no asm, no generic LD.E, no divergent branches.

#define TAB_N 57344  // floats staged in smem (224 KB), mult of 4

__global__ __launch_bounds__(1024, 1) void path_sampling_kernel(
    const int*   __restrict__ paths,      // [n_node, 32, 8]
    const int*   __restrict__ edge_ids,   // [n_node, 32, 7]
    const int*   __restrict__ rand_lens,  // [n_node, 32]
    const float* __restrict__ centrality, // [n_graph]
    float*       __restrict__ out_paths,  // [n_node, 8, 8] float32
    float*       __restrict__ out_edges,  // [n_node, 8, 7] float32
    int n_node)
{
    extern __shared__ float tab[];

    // ---- stage table prefix into smem (coalesced float4) ----
    {
        const float4* src = reinterpret_cast<const float4*>(centrality);
        float4*       dst = reinterpret_cast<float4*>(tab);
        for (int i = threadIdx.x; i < TAB_N / 4; i += 1024)
            dst[i] = src[i];
    }
    __syncthreads();

    const int lane        = threadIdx.x & 31;
    const int warp_local  = threadIdx.x >> 5;
    const int total_warps = gridDim.x << 5;  // 32 warps per block

#pragma unroll 2
    for (int node = (blockIdx.x << 5) + warp_local;
         node < n_node; node += total_warps) {

        // ---- load this lane's path row (coalesced int4 x2) + length ----
        const int4* prow = reinterpret_cast<const int4*>(paths + (node * 32 + lane) * 8);
        int4 p0 = __ldg(prow + 0);
        int4 p1 = __ldg(prow + 1);
        const int len = __ldg(rand_lens + node * 32 + lane);

        int mp[8] = {p0.x, p0.y, p0.z, p0.w, p1.x, p1.y, p1.z, p1.w};

        // ---- mask + branchless dual-source gather ----
        float score = 0.0f;
#pragma unroll
        for (int j = 0; j < 8; j++) {
            if (j > len) {
                mp[j] = -1;
            } else {
                int  id = mp[j];
                bool in_tab = id < TAB_N;
                float vs = tab[in_tab ? id : 0];                  // LDS, safe addr
                float vg = __ldg(centrality + (in_tab ? 0 : id)); // tail or bcast line0
                score += in_tab ? vs : vg;
            }
        }

        // ---- stable rank: higher score first, tie -> lower lane ----
        int rank = 0;
#pragma unroll
        for (int j = 0; j < 32; j++) {
            float sj = __shfl_sync(0xffffffffu, score, j);
            rank += (sj > score) || (sj == score && j < lane);
        }

        // ---- slot -> source lane map (lane r holds src lane of rank r) ----
        int my_src = 0;
#pragma unroll
        for (int r = 0; r < 8; r++) {
            unsigned mr = __ballot_sync(0xffffffffu, rank == r);
            if (lane == r) my_src = __ffs(mr) - 1;
        }

        // ---- selected lanes write their path row (float32) ----
        if (rank < 8) {
            float4* op = reinterpret_cast<float4*>(out_paths + (node * 8 + rank) * 8);
            op[0] = make_float4((float)mp[0], (float)mp[1], (float)mp[2], (float)mp[3]);
            op[1] = make_float4((float)mp[4], (float)mp[5], (float)mp[6], (float)mp[7]);
        }

        // ---- warp-cooperative edge copy: 56 contiguous floats/node ----
        const int* ebase = edge_ids + node * (32 * 7);
        float*     obase = out_edges + node * 56;
#pragma unroll
        for (int pass = 0; pass < 2; pass++) {
            int e = lane + pass * 32;
            int s = e / 7;
            int j = e - s * 7;
            int src = __shfl_sync(0xffffffffu, my_src, s & 7);
            if (e < 56) {
                obase[e] = (float)__ldg(ebase + src * 7 + j);
            }
        }
    }
}

extern "C" void kernel_launch(void* const* d_in, const int* in_sizes, int n_in,
                              void* d_out, int out_size) {
    // Bind inputs by DESCENDING element count (all distinct, order-agnostic):
    //   paths 25.6M > edge_ids 22.4M > rand_lens 3.2M > centrality 100K;
    //   size-1 k_path scalar ignored (constant 8).
    int idx[8];
    int m = 0;
    for (int i = 0; i < n_in && m < 8; i++) {
        if (in_sizes[i] > 1) idx[m++] = i;
    }
    for (int a = 1; a < m; a++) {
        int v = idx[a];
        int b = a - 1;
        while (b >= 0 && in_sizes[idx[b]] < in_sizes[v]) { idx[b + 1] = idx[b]; b--; }
        idx[b + 1] = v;
    }

    const int*   paths      = (const int*)  d_in[idx[0]];
    const int*   edge_ids   = (const int*)  d_in[idx[1]];
    const int*   rand_lens  = (const int*)  d_in[idx[2]];
    const float* centrality = (const float*)d_in[idx[3]];

    const int n_node = in_sizes[idx[0]] / (32 * 8);

    float* out_paths = (float*)d_out;                       // [n_node, 8, 8]
    float* out_edges = out_paths + (long long)n_node * 64;  // [n_node, 8, 7]

    const int smem_bytes = TAB_N * (int)sizeof(float);      // 229,376 B

    static int configured = -1;
    if (configured < 0) {
        cudaFuncSetAttribute(path_sampling_kernel,
                             cudaFuncAttributeMaxDynamicSharedMemorySize,
                             smem_bytes);
        configured = 1;
    }

    int dev = 0, sm_count = 148;
    cudaGetDevice(&dev);
    cudaDeviceGetAttribute(&sm_count, cudaDevAttrMultiProcessorCount, dev);

    path_sampling_kernel<<<sm_count, 1024, smem_bytes>>>(
        paths, edge_ids, rand_lens, centrality, out_paths, out_edges, n_node);
}

// round 11
// speedup vs baseline: 1.8985x; 1.7275x over previous
#include <cuda_runtime.h>
#include <cuda_bf16.h>

// PathSampling, R5 shape (warp-per-node, 256-thr blocks) + cache-policy split:
// streaming data (paths/lens/edges/outputs) uses evict-first (__ldcs/__stcs)
// so the 400KB centrality table keeps L1D residency; gathers stay __ldg.
// Selection math identical to R5 (exact fp32, stable tie-break).

__global__ __launch_bounds__(256) void path_sampling_kernel(
    const int*   __restrict__ paths,      // [n_node, 32, 8]
    const int*   __restrict__ edge_ids,   // [n_node, 32, 7]
    const int*   __restrict__ rand_lens,  // [n_node, 32]
    const float* __restrict__ centrality, // [n_graph]
    float*       __restrict__ out_paths,  // [n_node, 8, 8] float32
    float*       __restrict__ out_edges,  // [n_node, 8, 7] float32
    int n_node)
{
    const int warp_id = (blockIdx.x * blockDim.x + threadIdx.x) >> 5;
    const int lane    = threadIdx.x & 31;
    if (warp_id >= n_node) return;
    const long long node = warp_id;

    // ---- streaming loads: evict-first so they don't churn L1D ----
    const int4* prow = reinterpret_cast<const int4*>(paths + (node * 32 + lane) * 8);
    int4 p0 = __ldcs(prow + 0);
    int4 p1 = __ldcs(prow + 1);
    const int len = __ldcs(rand_lens + node * 32 + lane);

    int mp[8] = {p0.x, p0.y, p0.z, p0.w, p1.x, p1.y, p1.z, p1.w};

    // ---- mask (pos > len -> -1) + score; gathers keep normal caching ----
    float score = 0.0f;
#pragma unroll
    for (int j = 0; j < 8; j++) {
        if (j > len) {
            mp[j] = -1;
        } else {
            score += __ldg(centrality + mp[j]);
        }
    }

    // ---- stable rank among 32 lanes: higher score first, tie -> lower lane ----
    int rank = 0;
#pragma unroll
    for (int j = 0; j < 32; j++) {
        float sj = __shfl_sync(0xffffffffu, score, j);
        rank += (sj > score) || (sj == score && j < lane);
    }

    // ---- slot -> source lane map (lane r holds src lane of rank r) ----
    int my_src = 0;
#pragma unroll
    for (int r = 0; r < 8; r++) {
        unsigned mr = __ballot_sync(0xffffffffu, rank == r);
        if (lane == r) my_src = __ffs(mr) - 1;
    }

    // ---- selected lanes write their path row (float32, evict-first) ----
    if (rank < 8) {
        float4* op = reinterpret_cast<float4*>(out_paths + (node * 8 + rank) * 8);
        __stcs(op + 0, make_float4((float)mp[0], (float)mp[1], (float)mp[2], (float)mp[3]));
        __stcs(op + 1, make_float4((float)mp[4], (float)mp[5], (float)mp[6], (float)mp[7]));
    }

    // ---- warp-cooperative edge copy: 56 contiguous floats/node ----
    const int* ebase = edge_ids + node * (32 * 7);
    float*     obase = out_edges + node * 56;
#pragma unroll
    for (int pass = 0; pass < 2; pass++) {
        int e = lane + pass * 32;
        int s = e / 7;
        int j = e - s * 7;
        int src = __shfl_sync(0xffffffffu, my_src, s & 7);
        if (e < 56) {
            __stcs(obase + e, (float)__ldcs(ebase + src * 7 + j));
        }
    }
}

extern "C" void kernel_launch(void* const* d_in, const int* in_sizes, int n_in,
                              void* d_out, int out_size) {
    // Bind inputs by DESCENDING element count (all distinct, order-agnostic):
    //   paths 25.6M > edge_ids 22.4M > rand_lens 3.2M > centrality 100K;
    //   size-1 k_path scalar ignored (constant 8).
    int idx[8];
    int m = 0;
    for (int i = 0; i < n_in && m < 8; i++) {
        if (in_sizes[i] > 1) idx[m++] = i;
    }
    for (int a = 1; a < m; a++) {
        int v = idx[a];
        int b = a - 1;
        while (b >= 0 && in_sizes[idx[b]] < in_sizes[v]) { idx[b + 1] = idx[b]; b--; }
        idx[b + 1] = v;
    }

    const int*   paths      = (const int*)  d_in[idx[0]];
    const int*   edge_ids   = (const int*)  d_in[idx[1]];
    const int*   rand_lens  = (const int*)  d_in[idx[2]];
    const float* centrality = (const float*)d_in[idx[3]];

    const int n_node = in_sizes[idx[0]] / (32 * 8);

    float* out_paths = (float*)d_out;                       // [n_node, 8, 8]
    float* out_edges = out_paths + (long long)n_node * 64;  // [n_node, 8, 7]

    const int threads = 256;                  // 8 warps -> 8 nodes per block
    const int blocks  = (n_node + 7) / 8;
    path_sampling_kernel<<<blocks, threads>>>(paths, edge_ids, rand_lens,
                                              centrality, out_paths, out_edges,
                                              n_node);
}